// round 8
// baseline (speedup 1.0000x reference)
#include <cuda_runtime.h>
#include <cuda_bf16.h>
#include <cstdint>

// Problem dims
#define BB 8
#define SS 2048
#define DIN 1024
#define DOUT 64
#define ROWS_TOTAL (BB * SS)   // 16384
#define AP 72                  // padded bf16 row length (144 B) -> conflict-free ldmatrix

// Scratch for projected q/k/v (3 x 4 MB device globals; no allocs allowed)
__device__ float g_q[ROWS_TOTAL * DOUT];
__device__ float g_k[ROWS_TOTAL * DOUT];
__device__ float g_v[ROWS_TOTAL * DOUT];

// Pre-split, transposed weights: [w][kb][n][k_local] (kb = k/64)
__device__ __nv_bfloat16 g_Wh[3 * 16 * 64 * 64];
__device__ __nv_bfloat16 g_Wm[3 * 16 * 64 * 64];

// Mask dtype flag: 0 = uint8/bool, 1 = int32, 2 = float32
__device__ int g_mask_kind;

// ---------------------------------------------------------------------------
// helpers
// ---------------------------------------------------------------------------
static __device__ __forceinline__ uint32_t smem_u32(const void* p) {
    uint32_t a;
    asm("{ .reg .u64 t; cvta.to.shared.u64 t, %1; cvt.u32.u64 %0, t; }"
        : "=r"(a) : "l"(p));
    return a;
}
static __device__ __forceinline__ void ldsm_x4(uint32_t* r, uint32_t addr) {
    asm volatile("ldmatrix.sync.aligned.m8n8.x4.shared.b16 {%0,%1,%2,%3}, [%4];"
                 : "=r"(r[0]), "=r"(r[1]), "=r"(r[2]), "=r"(r[3]) : "r"(addr));
}
static __device__ __forceinline__ void ldsm_x2(uint32_t* r, uint32_t addr) {
    asm volatile("ldmatrix.sync.aligned.m8n8.x2.shared.b16 {%0,%1}, [%2];"
                 : "=r"(r[0]), "=r"(r[1]) : "r"(addr));
}
static __device__ __forceinline__ void mma16816(float* c, const uint32_t* a,
                                                const uint32_t* b) {
    asm volatile(
        "mma.sync.aligned.m16n8k16.row.col.f32.bf16.bf16.f32 "
        "{%0,%1,%2,%3}, {%4,%5,%6,%7}, {%8,%9}, {%0,%1,%2,%3};"
        : "+f"(c[0]), "+f"(c[1]), "+f"(c[2]), "+f"(c[3])
        : "r"(a[0]), "r"(a[1]), "r"(a[2]), "r"(a[3]), "r"(b[0]), "r"(b[1]));
}
static __device__ __forceinline__ void split2(float x, float y,
                                              uint32_t& hi, uint32_t& mid) {
    __nv_bfloat162 h = __floats2bfloat162_rn(x, y);
    __nv_bfloat162 m = __floats2bfloat162_rn(x - __bfloat162float(h.x),
                                             y - __bfloat162float(h.y));
    hi  = *(uint32_t*)&h;
    mid = *(uint32_t*)&m;
}
// fast 2^y on the FMA pipe; y <= 0 expected, clamped so exponent stays valid
static __device__ __forceinline__ float exp2_fast(float y) {
    y = fmaxf(y, -126.0f);
    float n = rintf(y);
    float f = y - n;                        // [-0.5, 0.5]
    float p = 1.3333558146428443e-3f;
    p = fmaf(p, f, 9.618129107628477e-3f);
    p = fmaf(p, f, 5.550410866482158e-2f);
    p = fmaf(p, f, 2.402265069591007e-1f);
    p = fmaf(p, f, 6.931471805599453e-1f);
    p = fmaf(p, f, 1.0f);
    float sc = __int_as_float(((int)n + 127) << 23);
    return p * sc;
}

// ---------------------------------------------------------------------------
// Kernel 0: sniff mask dtype (first 2048 words = 8 KB).
// ---------------------------------------------------------------------------
__global__ void detect_mask_kernel(const unsigned int* __restrict__ m)
{
    __shared__ int sawF, sawHigh;
    if (threadIdx.x == 0) { sawF = 0; sawHigh = 0; }
    __syncthreads();
    for (int i = threadIdx.x; i < 2048; i += 256) {
        unsigned int w = m[i];
        if (w == 0x3F800000u) sawF = 1;
        else if (w & 0xFFFFFF00u) sawHigh = 1;
    }
    __syncthreads();
    if (threadIdx.x == 0)
        g_mask_kind = sawF ? 2 : (sawHigh ? 0 : 1);
}

// ---------------------------------------------------------------------------
// Kernel P: split weights to bf16 hi/mid, transpose to [n][k] per K-block.
// ---------------------------------------------------------------------------
__global__ void prep_w_kernel(const float* __restrict__ Wq,
                              const float* __restrict__ Wk,
                              const float* __restrict__ Wv)
{
    int w = blockIdx.y;
    const float* W = (w == 0) ? Wq : (w == 1) ? Wk : Wv;
    int e = blockIdx.x * 256 + threadIdx.x;   // over [k][n]
    float x = W[e];
    int k = e >> 6, n = e & 63;
    __nv_bfloat16 hi = __float2bfloat16_rn(x);
    __nv_bfloat16 mid = __float2bfloat16_rn(x - __bfloat162float(hi));
    int o = w * 65536 + (k >> 6) * 4096 + n * 64 + (k & 63);
    g_Wh[o] = hi;
    g_Wm[o] = mid;
}

// ---------------------------------------------------------------------------
// Kernel 1: QKV projection via mma.sync bf16 3-MMA split (proven R6 version).
// ---------------------------------------------------------------------------
__global__ __launch_bounds__(256) void qkv_mma_kernel(
    const float* __restrict__ seq,
    const float* __restrict__ bq,
    const float* __restrict__ bk,
    const float* __restrict__ bv)
{
    extern __shared__ char smc[];
    __nv_bfloat16* Ah = (__nv_bfloat16*)smc;            // 128 x AP
    __nv_bfloat16* Am = Ah + 128 * AP;
    __nv_bfloat16* Bh = Am + 128 * AP;                  // 3 x 64 x AP
    __nv_bfloat16* Bm = Bh + 3 * 64 * AP;

    const int tid  = threadIdx.x;
    const int wid  = tid >> 5, lane = tid & 31;
    const int wm   = wid >> 1, wn = wid & 1;
    const int row0 = blockIdx.x * 128;
    const uint32_t sb  = smem_u32(smc);
    const uint32_t AhB = sb;
    const uint32_t AmB = sb + 128 * AP * 2;
    const uint32_t BhB = AmB + 128 * AP * 2;
    const uint32_t BmB = BhB + 3 * 64 * AP * 2;

    float cc[3][2][4][4];
#pragma unroll
    for (int w = 0; w < 3; w++)
#pragma unroll
        for (int mi = 0; mi < 2; mi++)
#pragma unroll
            for (int ni = 0; ni < 4; ni++)
#pragma unroll
                for (int r = 0; r < 4; r++) cc[w][mi][ni][r] = 0.0f;

    for (int kb = 0; kb < 16; kb++) {
        __syncthreads();
#pragma unroll
        for (int it = 0; it < 8; it++) {
            int f   = tid + it * 256;
            int row = f >> 4, k4 = f & 15;
            float4 t = *(const float4*)&seq[(size_t)(row0 + row) * DIN + kb * 64 + k4 * 4];
            uint32_t h0, m0, h1, m1;
            split2(t.x, t.y, h0, m0);
            split2(t.z, t.w, h1, m1);
            int off = row * AP + k4 * 4;
            *(uint32_t*)(Ah + off)     = h0;
            *(uint32_t*)(Ah + off + 2) = h1;
            *(uint32_t*)(Am + off)     = m0;
            *(uint32_t*)(Am + off + 2) = m1;
        }
        {
            const uint4* wh4 = (const uint4*)g_Wh;
            const uint4* wm4 = (const uint4*)g_Wm;
#pragma unroll
            for (int it = 0; it < 12; it++) {
                int u  = tid + it * 256;
                int sp = (u >= 1536);
                int u2 = u - sp * 1536;
                int w  = u2 >> 9;
                int r  = u2 & 511;
                int n  = r >> 3, ch = r & 7;
                uint4 val = (sp ? wm4 : wh4)[w * 8192 + kb * 512 + n * 8 + ch];
                __nv_bfloat16* dst = (sp ? Bm : Bh) + w * 64 * AP + n * AP + ch * 8;
                *(uint4*)dst = val;
            }
        }
        __syncthreads();

#pragma unroll
        for (int ks = 0; ks < 4; ks++) {
            const int k0 = ks * 16;
            uint32_t ah[2][4], am[2][4];
#pragma unroll
            for (int mi = 0; mi < 2; mi++) {
                uint32_t r = wm * 32 + mi * 16 + (lane & 15);
                uint32_t c = k0 + (lane >> 4) * 8;
                ldsm_x4(ah[mi], AhB + (r * AP + c) * 2);
                ldsm_x4(am[mi], AmB + (r * AP + c) * 2);
            }
#pragma unroll
            for (int w = 0; w < 3; w++) {
                const uint32_t base = w * 64 * AP * 2;
                uint32_t bh[4][2], bm[4][2];
#pragma unroll
                for (int ni = 0; ni < 4; ni++) {
                    uint32_t nr = wn * 32 + ni * 8 + (lane & 7);
                    uint32_t c  = k0 + ((lane >> 3) & 1) * 8;
                    ldsm_x2(bh[ni], BhB + base + (nr * AP + c) * 2);
                    ldsm_x2(bm[ni], BmB + base + (nr * AP + c) * 2);
                }
#pragma unroll
                for (int mi = 0; mi < 2; mi++)
#pragma unroll
                    for (int ni = 0; ni < 4; ni++) {
                        mma16816(cc[w][mi][ni], ah[mi], bh[ni]);
                        mma16816(cc[w][mi][ni], ah[mi], bm[ni]);
                        mma16816(cc[w][mi][ni], am[mi], bh[ni]);
                    }
            }
        }
    }

    const int g = lane >> 2, t4 = lane & 3;
#pragma unroll
    for (int w = 0; w < 3; w++) {
        const float* bias = (w == 0) ? bq : (w == 1) ? bk : bv;
        float* outp = (w == 0) ? g_q : (w == 1) ? g_k : g_v;
#pragma unroll
        for (int mi = 0; mi < 2; mi++)
#pragma unroll
            for (int ni = 0; ni < 4; ni++) {
                int row = row0 + wm * 32 + mi * 16 + g;
                int col = wn * 32 + ni * 8 + t4 * 2;
                float bx = bias[col], by = bias[col + 1];
                float2 r0 = make_float2(cc[w][mi][ni][0] + bx, cc[w][mi][ni][1] + by);
                float2 r1 = make_float2(cc[w][mi][ni][2] + bx, cc[w][mi][ni][3] + by);
                *(float2*)&outp[(size_t)row * 64 + col]       = r0;
                *(float2*)&outp[(size_t)(row + 8) * 64 + col] = r1;
            }
    }
}

// ---------------------------------------------------------------------------
// Kernel 2: register-resident flash-attention, 2 CTAs/SM for latency hiding.
// CTA = (batch, 128-query tile), 8 warps, each warp owns 16 query rows.
// ---------------------------------------------------------------------------
#define ASM_MF   0
#define ASM_BUF  256
#define ATTN_SMEM (ASM_BUF + 2 * 128 * AP * 2)   // 37120 B

__global__ __launch_bounds__(256, 2) void attn_mma_kernel(
    const void* __restrict__ mask_raw,
    float* __restrict__ out)
{
    extern __shared__ char smc[];
    float* Mf = (float*)(smc + ASM_MF);
    char*  buf = smc + ASM_BUF;
    __nv_bfloat16* QSH = (__nv_bfloat16*)buf;          // 128 x AP
    __nv_bfloat16* QSM = QSH + 128 * AP;
    __nv_bfloat16* Kh  = (__nv_bfloat16*)buf;          // 64 x AP (overlaps QS)
    __nv_bfloat16* Km  = Kh + 64 * AP;
    __nv_bfloat16* Vth = Km + 64 * AP;
    __nv_bfloat16* Vtm = Vth + 64 * AP;
    const uint32_t sb = smem_u32(buf);

    const int b   = blockIdx.y;
    const int q0  = blockIdx.x * 128;
    const int tid = threadIdx.x;
    const int wq  = tid >> 5, lane = tid & 31;
    const int g   = lane >> 2, t4 = lane & 3;
    const float kscale = rsqrtf((float)SS) * 1.4426950408889634f;  // log2 domain
    const int   mask_kind = g_mask_kind;

    // ---- Q staging + fragment load (once) ----
#pragma unroll
    for (int it = 0; it < 8; it++) {
        int f   = tid + it * 256;
        int row = f >> 4, k4 = f & 15;
        float4 t = *(const float4*)&g_q[(size_t)(b * SS + q0 + row) * 64 + k4 * 4];
        uint32_t h0, m0, h1, m1;
        split2(t.x, t.y, h0, m0);
        split2(t.z, t.w, h1, m1);
        int off = row * AP + k4 * 4;
        *(uint32_t*)(QSH + off)     = h0;
        *(uint32_t*)(QSH + off + 2) = h1;
        *(uint32_t*)(QSM + off)     = m0;
        *(uint32_t*)(QSM + off + 2) = m1;
    }
    __syncthreads();
    uint32_t qh[4][4], qm[4][4];
#pragma unroll
    for (int ks = 0; ks < 4; ks++) {
        uint32_t r = wq * 16 + (lane & 15);
        uint32_t c = ks * 16 + (lane >> 4) * 8;
        ldsm_x4(qh[ks], sb + (r * AP + c) * 2);
        ldsm_x4(qm[ks], sb + (128 * AP + r * AP + c) * 2);
    }

    float ov[8][4];
#pragma unroll
    for (int ni = 0; ni < 8; ni++)
#pragma unroll
        for (int r = 0; r < 4; r++) ov[ni][r] = 0.0f;
    float mrun0 = -1e30f, mrun1 = -1e30f, lrun0 = 0.0f, lrun1 = 0.0f;

    const uint32_t lrb = (lane & 7) + ((lane >> 4) & 1) * 8;   // B-operand row within 16
    const int vd  = tid & 63;        // V-fill: d index
    const int vkg = tid >> 6;        // V-fill: key group (16 keys)

    for (int kt = 0; kt < 32; kt++) {
        const int kg = kt * 64;
        __syncthreads();   // protect K/V (and first-iter Q staging) from readers

        // K fill (64 x 64 -> hi/mid, row-major)
#pragma unroll
        for (int it = 0; it < 4; it++) {
            int f   = tid + it * 256;
            int row = f >> 4, k4 = f & 15;
            float4 t = *(const float4*)&g_k[(size_t)(b * SS + kg + row) * 64 + k4 * 4];
            uint32_t h0, m0, h1, m1;
            split2(t.x, t.y, h0, m0);
            split2(t.z, t.w, h1, m1);
            int off = row * AP + k4 * 4;
            *(uint32_t*)(Kh + off)     = h0;
            *(uint32_t*)(Kh + off + 2) = h1;
            *(uint32_t*)(Km + off)     = m0;
            *(uint32_t*)(Km + off + 2) = m1;
        }
        // V transposed fill: Vt[d][kk], coalesced loads, paired bf16x2 stores
#pragma unroll
        for (int kp = 0; kp < 8; kp++) {
            int kk = vkg * 16 + kp * 2;
            float a  = g_v[(size_t)(b * SS + kg + kk)     * 64 + vd];
            float bb = g_v[(size_t)(b * SS + kg + kk + 1) * 64 + vd];
            uint32_t h, mm;
            split2(a, bb, h, mm);
            *(uint32_t*)&Vth[vd * AP + kk] = h;
            *(uint32_t*)&Vtm[vd * AP + kk] = mm;
        }
        if (tid < 64) {
            int idx = b * SS + kg + tid;
            bool mk;
            if (mask_kind == 2)      mk = ((const float*)mask_raw)[idx] != 0.0f;
            else if (mask_kind == 1) mk = ((const int*)mask_raw)[idx] != 0;
            else                     mk = ((const unsigned char*)mask_raw)[idx] != 0;
            Mf[tid] = mk ? 1.0f : 0.0f;
        }
        __syncthreads();

        // ---- QK^T (3-MMA split), S in registers ----
        float sc[8][4];
#pragma unroll
        for (int ni = 0; ni < 8; ni++)
#pragma unroll
            for (int r = 0; r < 4; r++) sc[ni][r] = 0.0f;

#pragma unroll
        for (int ks = 0; ks < 4; ks++) {
            const uint32_t cc = ks * 16 + ((lane >> 3) & 1) * 8;
#pragma unroll
            for (int grp = 0; grp < 4; grp++) {
                uint32_t kh4[4], km4[4];
                uint32_t nr = grp * 16 + lrb;
                ldsm_x4(kh4, sb + (nr * AP + cc) * 2);
                ldsm_x4(km4, sb + (64 * AP + nr * AP + cc) * 2);
                mma16816(sc[grp * 2],     qh[ks], kh4);
                mma16816(sc[grp * 2],     qh[ks], km4);
                mma16816(sc[grp * 2],     qm[ks], kh4);
                mma16816(sc[grp * 2 + 1], qh[ks], kh4 + 2);
                mma16816(sc[grp * 2 + 1], qh[ks], km4 + 2);
                mma16816(sc[grp * 2 + 1], qm[ks], kh4 + 2);
            }
        }

        // ---- in-register online softmax (log2 domain) ----
        float rmax0 = -1e30f, rmax1 = -1e30f;
#pragma unroll
        for (int ni = 0; ni < 8; ni++) {
            float2 mf = *(float2*)&Mf[ni * 8 + t4 * 2];
            sc[ni][0] = (mf.x != 0.0f) ? -1e9f : sc[ni][0] * kscale;
            sc[ni][1] = (mf.y != 0.0f) ? -1e9f : sc[ni][1] * kscale;
            sc[ni][2] = (mf.x != 0.0f) ? -1e9f : sc[ni][2] * kscale;
            sc[ni][3] = (mf.y != 0.0f) ? -1e9f : sc[ni][3] * kscale;
            rmax0 = fmaxf(rmax0, fmaxf(sc[ni][0], sc[ni][1]));
            rmax1 = fmaxf(rmax1, fmaxf(sc[ni][2], sc[ni][3]));
        }
        rmax0 = fmaxf(rmax0, __shfl_xor_sync(0xffffffffu, rmax0, 1));
        rmax0 = fmaxf(rmax0, __shfl_xor_sync(0xffffffffu, rmax0, 2));
        rmax1 = fmaxf(rmax1, __shfl_xor_sync(0xffffffffu, rmax1, 1));
        rmax1 = fmaxf(rmax1, __shfl_xor_sync(0xffffffffu, rmax1, 2));
        float mn0 = fmaxf(mrun0, rmax0);
        float mn1 = fmaxf(mrun1, rmax1);
        float alpha0 = exp2_fast(mrun0 - mn0);
        float alpha1 = exp2_fast(mrun1 - mn1);
        mrun0 = mn0;
        mrun1 = mn1;
        float rs0 = 0.0f, rs1 = 0.0f;
#pragma unroll
        for (int ni = 0; ni < 8; ni++) {
            sc[ni][0] = exp2_fast(sc[ni][0] - mn0);
            sc[ni][1] = exp2_fast(sc[ni][1] - mn0);
            sc[ni][2] = exp2_fast(sc[ni][2] - mn1);
            sc[ni][3] = exp2_fast(sc[ni][3] - mn1);
            rs0 += sc[ni][0] + sc[ni][1];
            rs1 += sc[ni][2] + sc[ni][3];
        }
        rs0 += __shfl_xor_sync(0xffffffffu, rs0, 1);
        rs0 += __shfl_xor_sync(0xffffffffu, rs0, 2);
        rs1 += __shfl_xor_sync(0xffffffffu, rs1, 1);
        rs1 += __shfl_xor_sync(0xffffffffu, rs1, 2);
        lrun0 = lrun0 * alpha0 + rs0;
        lrun1 = lrun1 * alpha1 + rs1;

        // ---- rescale O, then PV (P packed from registers; V from smem) ----
#pragma unroll
        for (int ni = 0; ni < 8; ni++) {
            ov[ni][0] *= alpha0;
            ov[ni][1] *= alpha0;
            ov[ni][2] *= alpha1;
            ov[ni][3] *= alpha1;
        }
#pragma unroll
        for (int ks = 0; ks < 4; ks++) {
            uint32_t pah[4], pam[4];
            split2(sc[2 * ks][0],     sc[2 * ks][1],     pah[0], pam[0]);
            split2(sc[2 * ks][2],     sc[2 * ks][3],     pah[1], pam[1]);
            split2(sc[2 * ks + 1][0], sc[2 * ks + 1][1], pah[2], pam[2]);
            split2(sc[2 * ks + 1][2], sc[2 * ks + 1][3], pah[3], pam[3]);
            const uint32_t cc = ks * 16 + ((lane >> 3) & 1) * 8;
#pragma unroll
            for (int grp = 0; grp < 4; grp++) {
                uint32_t vh4[4], vm4[4];
                uint32_t nr = grp * 16 + lrb;
                ldsm_x4(vh4, sb + (2 * 64 * AP + nr * AP + cc) * 2);
                ldsm_x4(vm4, sb + (3 * 64 * AP + nr * AP + cc) * 2);
                mma16816(ov[grp * 2],     pah, vh4);
                mma16816(ov[grp * 2],     pah, vm4);
                mma16816(ov[grp * 2],     pam, vh4);
                mma16816(ov[grp * 2 + 1], pah, vh4 + 2);
                mma16816(ov[grp * 2 + 1], pah, vm4 + 2);
                mma16816(ov[grp * 2 + 1], pam, vh4 + 2);
            }
        }
    }

    // ---- final: divide by l, write out ----
    const float il0 = 1.0f / lrun0;
    const float il1 = 1.0f / lrun1;
    const int row = q0 + wq * 16 + g;
#pragma unroll
    for (int ni = 0; ni < 8; ni++) {
        int col = ni * 8 + t4 * 2;
        *(float2*)&out[((size_t)(b * SS) + row) * 64 + col] =
            make_float2(ov[ni][0] * il0, ov[ni][1] * il0);
        *(float2*)&out[((size_t)(b * SS) + row + 8) * 64 + col] =
            make_float2(ov[ni][2] * il1, ov[ni][3] * il1);
    }
}

// ---------------------------------------------------------------------------
extern "C" void kernel_launch(void* const* d_in, const int* in_sizes, int n_in,
                              void* d_out, int out_size)
{
    const float* seq  = (const float*)d_in[0];
    const void*  mask = d_in[1];
    const float* Wq   = (const float*)d_in[2];
    const float* bq   = (const float*)d_in[3];
    const float* Wk   = (const float*)d_in[4];
    const float* bk   = (const float*)d_in[5];
    const float* Wv   = (const float*)d_in[6];
    const float* bv   = (const float*)d_in[7];
    float* out = (float*)d_out;

    const int qkv_smem = (2 * 128 + 6 * 64) * AP * 2;   // 92160
    cudaFuncSetAttribute(qkv_mma_kernel,
                         cudaFuncAttributeMaxDynamicSharedMemorySize, qkv_smem);
    cudaFuncSetAttribute(attn_mma_kernel,
                         cudaFuncAttributeMaxDynamicSharedMemorySize, ATTN_SMEM);

    detect_mask_kernel<<<1, 256>>>((const unsigned int*)mask);
    prep_w_kernel<<<dim3(256, 3), 256>>>(Wq, Wk, Wv);
    qkv_mma_kernel<<<ROWS_TOTAL / 128, 256, qkv_smem>>>(seq, bq, bk, bv);
    attn_mma_kernel<<<dim3(SS / 128, BB), 256, ATTN_SMEM>>>(mask, out);
}

// round 9
// speedup vs baseline: 1.1778x; 1.1778x over previous
#include <cuda_runtime.h>
#include <cuda_bf16.h>
#include <cstdint>

// Problem dims
#define BB 8
#define SS 2048
#define DIN 1024
#define DOUT 64
#define ROWS_TOTAL (BB * SS)   // 16384
#define AP 72                  // padded bf16 row length (144 B) -> conflict-free ldmatrix

// Scratch for projected q/k/v (3 x 4 MB device globals; no allocs allowed)
__device__ float g_q[ROWS_TOTAL * DOUT];
__device__ float g_k[ROWS_TOTAL * DOUT];
__device__ float g_v[ROWS_TOTAL * DOUT];

// Pre-split, transposed weights: [w][kb][n][k_local] (kb = k/64)
__device__ __nv_bfloat16 g_Wh[3 * 16 * 64 * 64];
__device__ __nv_bfloat16 g_Wm[3 * 16 * 64 * 64];

// Mask dtype flag: 0 = uint8/bool, 1 = int32, 2 = float32
__device__ int g_mask_kind;

// ---------------------------------------------------------------------------
// helpers
// ---------------------------------------------------------------------------
static __device__ __forceinline__ uint32_t smem_u32(const void* p) {
    uint32_t a;
    asm("{ .reg .u64 t; cvta.to.shared.u64 t, %1; cvt.u32.u64 %0, t; }"
        : "=r"(a) : "l"(p));
    return a;
}
static __device__ __forceinline__ void ldsm_x4(uint32_t* r, uint32_t addr) {
    asm volatile("ldmatrix.sync.aligned.m8n8.x4.shared.b16 {%0,%1,%2,%3}, [%4];"
                 : "=r"(r[0]), "=r"(r[1]), "=r"(r[2]), "=r"(r[3]) : "r"(addr));
}
static __device__ __forceinline__ void ldsm_x2(uint32_t* r, uint32_t addr) {
    asm volatile("ldmatrix.sync.aligned.m8n8.x2.shared.b16 {%0,%1}, [%2];"
                 : "=r"(r[0]), "=r"(r[1]) : "r"(addr));
}
static __device__ __forceinline__ void mma16816(float* c, const uint32_t* a,
                                                const uint32_t* b) {
    asm volatile(
        "mma.sync.aligned.m16n8k16.row.col.f32.bf16.bf16.f32 "
        "{%0,%1,%2,%3}, {%4,%5,%6,%7}, {%8,%9}, {%0,%1,%2,%3};"
        : "+f"(c[0]), "+f"(c[1]), "+f"(c[2]), "+f"(c[3])
        : "r"(a[0]), "r"(a[1]), "r"(a[2]), "r"(a[3]), "r"(b[0]), "r"(b[1]));
}
static __device__ __forceinline__ void split2(float x, float y,
                                              uint32_t& hi, uint32_t& mid) {
    __nv_bfloat162 h = __floats2bfloat162_rn(x, y);
    __nv_bfloat162 m = __floats2bfloat162_rn(x - __bfloat162float(h.x),
                                             y - __bfloat162float(h.y));
    hi  = *(uint32_t*)&h;
    mid = *(uint32_t*)&m;
}
// fast 2^y on the FMA pipe; y <= 0 expected, clamped so exponent stays valid
static __device__ __forceinline__ float exp2_fast(float y) {
    y = fmaxf(y, -126.0f);
    float n = rintf(y);
    float f = y - n;                        // [-0.5, 0.5]
    float p = 1.3333558146428443e-3f;
    p = fmaf(p, f, 9.618129107628477e-3f);
    p = fmaf(p, f, 5.550410866482158e-2f);
    p = fmaf(p, f, 2.402265069591007e-1f);
    p = fmaf(p, f, 6.931471805599453e-1f);
    p = fmaf(p, f, 1.0f);
    float sc = __int_as_float(((int)n + 127) << 23);
    return p * sc;
}

// ---------------------------------------------------------------------------
// Kernel 0: sniff mask dtype (first 2048 words = 8 KB).
// ---------------------------------------------------------------------------
__global__ void detect_mask_kernel(const unsigned int* __restrict__ m)
{
    __shared__ int sawF, sawHigh;
    if (threadIdx.x == 0) { sawF = 0; sawHigh = 0; }
    __syncthreads();
    for (int i = threadIdx.x; i < 2048; i += 256) {
        unsigned int w = m[i];
        if (w == 0x3F800000u) sawF = 1;
        else if (w & 0xFFFFFF00u) sawHigh = 1;
    }
    __syncthreads();
    if (threadIdx.x == 0)
        g_mask_kind = sawF ? 2 : (sawHigh ? 0 : 1);
}

// ---------------------------------------------------------------------------
// Kernel P: split weights to bf16 hi/mid, transpose to [n][k] per K-block.
// ---------------------------------------------------------------------------
__global__ void prep_w_kernel(const float* __restrict__ Wq,
                              const float* __restrict__ Wk,
                              const float* __restrict__ Wv)
{
    int w = blockIdx.y;
    const float* W = (w == 0) ? Wq : (w == 1) ? Wk : Wv;
    int e = blockIdx.x * 256 + threadIdx.x;   // over [k][n]
    float x = W[e];
    int k = e >> 6, n = e & 63;
    __nv_bfloat16 hi = __float2bfloat16_rn(x);
    __nv_bfloat16 mid = __float2bfloat16_rn(x - __bfloat162float(hi));
    int o = w * 65536 + (k >> 6) * 4096 + n * 64 + (k & 63);
    g_Wh[o] = hi;
    g_Wm[o] = mid;
}

// ---------------------------------------------------------------------------
// Kernel 1: QKV projection via mma.sync bf16 3-MMA split (proven R6 version).
// ---------------------------------------------------------------------------
__global__ __launch_bounds__(256) void qkv_mma_kernel(
    const float* __restrict__ seq,
    const float* __restrict__ bq,
    const float* __restrict__ bk,
    const float* __restrict__ bv)
{
    extern __shared__ char smc[];
    __nv_bfloat16* Ah = (__nv_bfloat16*)smc;            // 128 x AP
    __nv_bfloat16* Am = Ah + 128 * AP;
    __nv_bfloat16* Bh = Am + 128 * AP;                  // 3 x 64 x AP
    __nv_bfloat16* Bm = Bh + 3 * 64 * AP;

    const int tid  = threadIdx.x;
    const int wid  = tid >> 5, lane = tid & 31;
    const int wm   = wid >> 1, wn = wid & 1;
    const int row0 = blockIdx.x * 128;
    const uint32_t sb  = smem_u32(smc);
    const uint32_t AhB = sb;
    const uint32_t AmB = sb + 128 * AP * 2;
    const uint32_t BhB = AmB + 128 * AP * 2;
    const uint32_t BmB = BhB + 3 * 64 * AP * 2;

    float cc[3][2][4][4];
#pragma unroll
    for (int w = 0; w < 3; w++)
#pragma unroll
        for (int mi = 0; mi < 2; mi++)
#pragma unroll
            for (int ni = 0; ni < 4; ni++)
#pragma unroll
                for (int r = 0; r < 4; r++) cc[w][mi][ni][r] = 0.0f;

    for (int kb = 0; kb < 16; kb++) {
        __syncthreads();
#pragma unroll
        for (int it = 0; it < 8; it++) {
            int f   = tid + it * 256;
            int row = f >> 4, k4 = f & 15;
            float4 t = *(const float4*)&seq[(size_t)(row0 + row) * DIN + kb * 64 + k4 * 4];
            uint32_t h0, m0, h1, m1;
            split2(t.x, t.y, h0, m0);
            split2(t.z, t.w, h1, m1);
            int off = row * AP + k4 * 4;
            *(uint32_t*)(Ah + off)     = h0;
            *(uint32_t*)(Ah + off + 2) = h1;
            *(uint32_t*)(Am + off)     = m0;
            *(uint32_t*)(Am + off + 2) = m1;
        }
        {
            const uint4* wh4 = (const uint4*)g_Wh;
            const uint4* wm4 = (const uint4*)g_Wm;
#pragma unroll
            for (int it = 0; it < 12; it++) {
                int u  = tid + it * 256;
                int sp = (u >= 1536);
                int u2 = u - sp * 1536;
                int w  = u2 >> 9;
                int r  = u2 & 511;
                int n  = r >> 3, ch = r & 7;
                uint4 val = (sp ? wm4 : wh4)[w * 8192 + kb * 512 + n * 8 + ch];
                __nv_bfloat16* dst = (sp ? Bm : Bh) + w * 64 * AP + n * AP + ch * 8;
                *(uint4*)dst = val;
            }
        }
        __syncthreads();

#pragma unroll
        for (int ks = 0; ks < 4; ks++) {
            const int k0 = ks * 16;
            uint32_t ah[2][4], am[2][4];
#pragma unroll
            for (int mi = 0; mi < 2; mi++) {
                uint32_t r = wm * 32 + mi * 16 + (lane & 15);
                uint32_t c = k0 + (lane >> 4) * 8;
                ldsm_x4(ah[mi], AhB + (r * AP + c) * 2);
                ldsm_x4(am[mi], AmB + (r * AP + c) * 2);
            }
#pragma unroll
            for (int w = 0; w < 3; w++) {
                const uint32_t base = w * 64 * AP * 2;
                uint32_t bh[4][2], bm[4][2];
#pragma unroll
                for (int ni = 0; ni < 4; ni++) {
                    uint32_t nr = wn * 32 + ni * 8 + (lane & 7);
                    uint32_t c  = k0 + ((lane >> 3) & 1) * 8;
                    ldsm_x2(bh[ni], BhB + base + (nr * AP + c) * 2);
                    ldsm_x2(bm[ni], BmB + base + (nr * AP + c) * 2);
                }
#pragma unroll
                for (int mi = 0; mi < 2; mi++)
#pragma unroll
                    for (int ni = 0; ni < 4; ni++) {
                        mma16816(cc[w][mi][ni], ah[mi], bh[ni]);
                        mma16816(cc[w][mi][ni], ah[mi], bm[ni]);
                        mma16816(cc[w][mi][ni], am[mi], bh[ni]);
                    }
            }
        }
    }

    const int g = lane >> 2, t4 = lane & 3;
#pragma unroll
    for (int w = 0; w < 3; w++) {
        const float* bias = (w == 0) ? bq : (w == 1) ? bk : bv;
        float* outp = (w == 0) ? g_q : (w == 1) ? g_k : g_v;
#pragma unroll
        for (int mi = 0; mi < 2; mi++)
#pragma unroll
            for (int ni = 0; ni < 4; ni++) {
                int row = row0 + wm * 32 + mi * 16 + g;
                int col = wn * 32 + ni * 8 + t4 * 2;
                float bx = bias[col], by = bias[col + 1];
                float2 r0 = make_float2(cc[w][mi][ni][0] + bx, cc[w][mi][ni][1] + by);
                float2 r1 = make_float2(cc[w][mi][ni][2] + bx, cc[w][mi][ni][3] + by);
                *(float2*)&outp[(size_t)row * 64 + col]       = r0;
                *(float2*)&outp[(size_t)(row + 8) * 64 + col] = r1;
            }
    }
}

// ---------------------------------------------------------------------------
// Kernel 2: register-resident flash-attention with register-prefetch pipeline.
// CTA = (batch, 128-query tile), 8 warps, each warp owns 16 query rows.
// Global K/V loads for tile t+1 are issued before tile t's compute so the
// MMA/softmax body hides their latency (no launch-bounds cap; 1 CTA/SM).
// ---------------------------------------------------------------------------
#define ASM_MF   0
#define ASM_BUF  256
#define ATTN_SMEM (ASM_BUF + 2 * 128 * AP * 2)   // 37120 B

__global__ __launch_bounds__(256) void attn_mma_kernel(
    const void* __restrict__ mask_raw,
    float* __restrict__ out)
{
    extern __shared__ char smc[];
    float* Mf = (float*)(smc + ASM_MF);
    char*  buf = smc + ASM_BUF;
    __nv_bfloat16* QSH = (__nv_bfloat16*)buf;          // 128 x AP
    __nv_bfloat16* QSM = QSH + 128 * AP;
    __nv_bfloat16* Kh  = (__nv_bfloat16*)buf;          // 64 x AP (overlaps QS)
    __nv_bfloat16* Km  = Kh + 64 * AP;
    __nv_bfloat16* Vth = Km + 64 * AP;
    __nv_bfloat16* Vtm = Vth + 64 * AP;
    const uint32_t sb = smem_u32(buf);

    const int b   = blockIdx.y;
    const int q0  = blockIdx.x * 128;
    const int tid = threadIdx.x;
    const int wq  = tid >> 5, lane = tid & 31;
    const int g   = lane >> 2, t4 = lane & 3;
    const float kscale = rsqrtf((float)SS) * 1.4426950408889634f;  // log2 domain
    const int   mask_kind = g_mask_kind;

    // ---- Q staging + fragment load (once) ----
#pragma unroll
    for (int it = 0; it < 8; it++) {
        int f   = tid + it * 256;
        int row = f >> 4, k4 = f & 15;
        float4 t = *(const float4*)&g_q[(size_t)(b * SS + q0 + row) * 64 + k4 * 4];
        uint32_t h0, m0, h1, m1;
        split2(t.x, t.y, h0, m0);
        split2(t.z, t.w, h1, m1);
        int off = row * AP + k4 * 4;
        *(uint32_t*)(QSH + off)     = h0;
        *(uint32_t*)(QSH + off + 2) = h1;
        *(uint32_t*)(QSM + off)     = m0;
        *(uint32_t*)(QSM + off + 2) = m1;
    }
    __syncthreads();
    uint32_t qh[4][4], qm[4][4];
#pragma unroll
    for (int ks = 0; ks < 4; ks++) {
        uint32_t r = wq * 16 + (lane & 15);
        uint32_t c = ks * 16 + (lane >> 4) * 8;
        ldsm_x4(qh[ks], sb + (r * AP + c) * 2);
        ldsm_x4(qm[ks], sb + (128 * AP + r * AP + c) * 2);
    }

    float ov[8][4];
#pragma unroll
    for (int ni = 0; ni < 8; ni++)
#pragma unroll
        for (int r = 0; r < 4; r++) ov[ni][r] = 0.0f;
    float mrun0 = -1e30f, mrun1 = -1e30f, lrun0 = 0.0f, lrun1 = 0.0f;

    const uint32_t lrb = (lane & 7) + ((lane >> 4) & 1) * 8;   // B-operand row within 16
    const int vd   = tid & 63;       // V-fill: d index
    const int vkg  = tid >> 6;       // V-fill: key group (16 keys)
    const int krow = tid >> 4;       // K-fill: row (0..15 stride 16 -> 4 rows/thread)
    const int kk4  = tid & 15;       // K-fill: float4 column

    // ---- prefetch registers (tile 0) ----
    float4 kpre[4];
    float  vpa[8], vpb[8];
    float  mpre = 0.0f;
    {
        const int kg = 0;
#pragma unroll
        for (int it = 0; it < 4; it++)
            kpre[it] = *(const float4*)&g_k[(size_t)(b * SS + kg + krow + it * 16) * 64 + kk4 * 4];
#pragma unroll
        for (int kp = 0; kp < 8; kp++) {
            int kk = vkg * 16 + kp * 2;
            vpa[kp] = g_v[(size_t)(b * SS + kg + kk)     * 64 + vd];
            vpb[kp] = g_v[(size_t)(b * SS + kg + kk + 1) * 64 + vd];
        }
        if (tid < 64) {
            int idx = b * SS + kg + tid;
            bool mk;
            if (mask_kind == 2)      mk = ((const float*)mask_raw)[idx] != 0.0f;
            else if (mask_kind == 1) mk = ((const int*)mask_raw)[idx] != 0;
            else                     mk = ((const unsigned char*)mask_raw)[idx] != 0;
            mpre = mk ? 1.0f : 0.0f;
        }
    }

    for (int kt = 0; kt < 32; kt++) {
        __syncthreads();   // previous compute (or Q-frag ldsm) done with smem

        // ---- store prefetched tile -> smem (hi/mid split at store time) ----
#pragma unroll
        for (int it = 0; it < 4; it++) {
            float4 t = kpre[it];
            uint32_t h0, m0, h1, m1;
            split2(t.x, t.y, h0, m0);
            split2(t.z, t.w, h1, m1);
            int off = (krow + it * 16) * AP + kk4 * 4;
            *(uint32_t*)(Kh + off)     = h0;
            *(uint32_t*)(Kh + off + 2) = h1;
            *(uint32_t*)(Km + off)     = m0;
            *(uint32_t*)(Km + off + 2) = m1;
        }
#pragma unroll
        for (int kp = 0; kp < 8; kp++) {
            int kk = vkg * 16 + kp * 2;
            uint32_t h, mm;
            split2(vpa[kp], vpb[kp], h, mm);
            *(uint32_t*)&Vth[vd * AP + kk] = h;
            *(uint32_t*)&Vtm[vd * AP + kk] = mm;
        }
        if (tid < 64) Mf[tid] = mpre;
        __syncthreads();

        // ---- issue prefetch for tile kt+1 (latency hidden by compute) ----
        if (kt + 1 < 32) {
            const int kg = (kt + 1) * 64;
#pragma unroll
            for (int it = 0; it < 4; it++)
                kpre[it] = *(const float4*)&g_k[(size_t)(b * SS + kg + krow + it * 16) * 64 + kk4 * 4];
#pragma unroll
            for (int kp = 0; kp < 8; kp++) {
                int kk = vkg * 16 + kp * 2;
                vpa[kp] = g_v[(size_t)(b * SS + kg + kk)     * 64 + vd];
                vpb[kp] = g_v[(size_t)(b * SS + kg + kk + 1) * 64 + vd];
            }
            if (tid < 64) {
                int idx = b * SS + kg + tid;
                bool mk;
                if (mask_kind == 2)      mk = ((const float*)mask_raw)[idx] != 0.0f;
                else if (mask_kind == 1) mk = ((const int*)mask_raw)[idx] != 0;
                else                     mk = ((const unsigned char*)mask_raw)[idx] != 0;
                mpre = mk ? 1.0f : 0.0f;
            }
        }

        // ---- QK^T (3-MMA split), S in registers ----
        float sc[8][4];
#pragma unroll
        for (int ni = 0; ni < 8; ni++)
#pragma unroll
            for (int r = 0; r < 4; r++) sc[ni][r] = 0.0f;

#pragma unroll
        for (int ks = 0; ks < 4; ks++) {
            const uint32_t cc = ks * 16 + ((lane >> 3) & 1) * 8;
#pragma unroll
            for (int grp = 0; grp < 4; grp++) {
                uint32_t kh4[4], km4[4];
                uint32_t nr = grp * 16 + lrb;
                ldsm_x4(kh4, sb + (nr * AP + cc) * 2);
                ldsm_x4(km4, sb + (64 * AP + nr * AP + cc) * 2);
                mma16816(sc[grp * 2],     qh[ks], kh4);
                mma16816(sc[grp * 2],     qh[ks], km4);
                mma16816(sc[grp * 2],     qm[ks], kh4);
                mma16816(sc[grp * 2 + 1], qh[ks], kh4 + 2);
                mma16816(sc[grp * 2 + 1], qh[ks], km4 + 2);
                mma16816(sc[grp * 2 + 1], qm[ks], kh4 + 2);
            }
        }

        // ---- in-register online softmax (log2 domain) ----
        float rmax0 = -1e30f, rmax1 = -1e30f;
#pragma unroll
        for (int ni = 0; ni < 8; ni++) {
            float2 mf = *(float2*)&Mf[ni * 8 + t4 * 2];
            sc[ni][0] = (mf.x != 0.0f) ? -1e9f : sc[ni][0] * kscale;
            sc[ni][1] = (mf.y != 0.0f) ? -1e9f : sc[ni][1] * kscale;
            sc[ni][2] = (mf.x != 0.0f) ? -1e9f : sc[ni][2] * kscale;
            sc[ni][3] = (mf.y != 0.0f) ? -1e9f : sc[ni][3] * kscale;
            rmax0 = fmaxf(rmax0, fmaxf(sc[ni][0], sc[ni][1]));
            rmax1 = fmaxf(rmax1, fmaxf(sc[ni][2], sc[ni][3]));
        }
        rmax0 = fmaxf(rmax0, __shfl_xor_sync(0xffffffffu, rmax0, 1));
        rmax0 = fmaxf(rmax0, __shfl_xor_sync(0xffffffffu, rmax0, 2));
        rmax1 = fmaxf(rmax1, __shfl_xor_sync(0xffffffffu, rmax1, 1));
        rmax1 = fmaxf(rmax1, __shfl_xor_sync(0xffffffffu, rmax1, 2));
        float mn0 = fmaxf(mrun0, rmax0);
        float mn1 = fmaxf(mrun1, rmax1);
        float alpha0 = exp2_fast(mrun0 - mn0);
        float alpha1 = exp2_fast(mrun1 - mn1);
        mrun0 = mn0;
        mrun1 = mn1;
        float rs0 = 0.0f, rs1 = 0.0f;
#pragma unroll
        for (int ni = 0; ni < 8; ni++) {
            sc[ni][0] = exp2_fast(sc[ni][0] - mn0);
            sc[ni][1] = exp2_fast(sc[ni][1] - mn0);
            sc[ni][2] = exp2_fast(sc[ni][2] - mn1);
            sc[ni][3] = exp2_fast(sc[ni][3] - mn1);
            rs0 += sc[ni][0] + sc[ni][1];
            rs1 += sc[ni][2] + sc[ni][3];
        }
        rs0 += __shfl_xor_sync(0xffffffffu, rs0, 1);
        rs0 += __shfl_xor_sync(0xffffffffu, rs0, 2);
        rs1 += __shfl_xor_sync(0xffffffffu, rs1, 1);
        rs1 += __shfl_xor_sync(0xffffffffu, rs1, 2);
        lrun0 = lrun0 * alpha0 + rs0;
        lrun1 = lrun1 * alpha1 + rs1;

        // ---- rescale O, then PV (P packed from registers; V from smem) ----
#pragma unroll
        for (int ni = 0; ni < 8; ni++) {
            ov[ni][0] *= alpha0;
            ov[ni][1] *= alpha0;
            ov[ni][2] *= alpha1;
            ov[ni][3] *= alpha1;
        }
#pragma unroll
        for (int ks = 0; ks < 4; ks++) {
            uint32_t pah[4], pam[4];
            split2(sc[2 * ks][0],     sc[2 * ks][1],     pah[0], pam[0]);
            split2(sc[2 * ks][2],     sc[2 * ks][3],     pah[1], pam[1]);
            split2(sc[2 * ks + 1][0], sc[2 * ks + 1][1], pah[2], pam[2]);
            split2(sc[2 * ks + 1][2], sc[2 * ks + 1][3], pah[3], pam[3]);
            const uint32_t cc = ks * 16 + ((lane >> 3) & 1) * 8;
#pragma unroll
            for (int grp = 0; grp < 4; grp++) {
                uint32_t vh4[4], vm4[4];
                uint32_t nr = grp * 16 + lrb;
                ldsm_x4(vh4, sb + (2 * 64 * AP + nr * AP + cc) * 2);
                ldsm_x4(vm4, sb + (3 * 64 * AP + nr * AP + cc) * 2);
                mma16816(ov[grp * 2],     pah, vh4);
                mma16816(ov[grp * 2],     pah, vm4);
                mma16816(ov[grp * 2],     pam, vh4);
                mma16816(ov[grp * 2 + 1], pah, vh4 + 2);
                mma16816(ov[grp * 2 + 1], pah, vm4 + 2);
                mma16816(ov[grp * 2 + 1], pam, vh4 + 2);
            }
        }
    }

    // ---- final: divide by l, write out ----
    const float il0 = 1.0f / lrun0;
    const float il1 = 1.0f / lrun1;
    const int row = q0 + wq * 16 + g;
#pragma unroll
    for (int ni = 0; ni < 8; ni++) {
        int col = ni * 8 + t4 * 2;
        *(float2*)&out[((size_t)(b * SS) + row) * 64 + col] =
            make_float2(ov[ni][0] * il0, ov[ni][1] * il0);
        *(float2*)&out[((size_t)(b * SS) + row + 8) * 64 + col] =
            make_float2(ov[ni][2] * il1, ov[ni][3] * il1);
    }
}

// ---------------------------------------------------------------------------
extern "C" void kernel_launch(void* const* d_in, const int* in_sizes, int n_in,
                              void* d_out, int out_size)
{
    const float* seq  = (const float*)d_in[0];
    const void*  mask = d_in[1];
    const float* Wq   = (const float*)d_in[2];
    const float* bq   = (const float*)d_in[3];
    const float* Wk   = (const float*)d_in[4];
    const float* bk   = (const float*)d_in[5];
    const float* Wv   = (const float*)d_in[6];
    const float* bv   = (const float*)d_in[7];
    float* out = (float*)d_out;

    const int qkv_smem = (2 * 128 + 6 * 64) * AP * 2;   // 92160
    cudaFuncSetAttribute(qkv_mma_kernel,
                         cudaFuncAttributeMaxDynamicSharedMemorySize, qkv_smem);
    cudaFuncSetAttribute(attn_mma_kernel,
                         cudaFuncAttributeMaxDynamicSharedMemorySize, ATTN_SMEM);

    detect_mask_kernel<<<1, 256>>>((const unsigned int*)mask);
    prep_w_kernel<<<dim3(256, 3), 256>>>(Wq, Wk, Wv);
    qkv_mma_kernel<<<ROWS_TOTAL / 128, 256, qkv_smem>>>(seq, bq, bk, bv);
    attn_mma_kernel<<<dim3(SS / 128, BB), 256, ATTN_SMEM>>>(mask, out);
}